// round 1
// baseline (speedup 1.0000x reference)
#include <cuda_runtime.h>

typedef unsigned long long u64;

#define BATCH 8
#define CH    64
#define HW    4096
#define CQn   8
#define CVn   32
#define NP    1024   // pooled pixels per batch (32x32)

// ---------------- folded weights + precomputed Q/K/V ----------------
__device__ float g_WQ[CQn*CH], g_CQ[CQn];
__device__ float g_WK[CQn*CH], g_CK[CQn];
__device__ float g_WV[CVn*CH], g_CV[CVn];
__device__ float g_WP[CH*CVn], g_CP[CH];
__device__ float g_Q[(size_t)BATCH*HW*CQn];   // [b][n][8]
__device__ float g_K[(size_t)BATCH*NP*CQn];   // [b][m][8]
__device__ float g_V[(size_t)BATCH*NP*CVn];   // [b][m][32]

// ---------------- f32x2 helpers (Blackwell packed fp32) ----------------
__device__ __forceinline__ u64 pk2(float lo, float hi) {
    u64 r; asm("mov.b64 %0,{%1,%2};" : "=l"(r) : "f"(lo), "f"(hi)); return r;
}
__device__ __forceinline__ void upk2(u64 v, float& lo, float& hi) {
    asm("mov.b64 {%0,%1},%2;" : "=f"(lo), "=f"(hi) : "l"(v));
}
__device__ __forceinline__ u64 ffma2(u64 a, u64 b, u64 c) {
    u64 d; asm("fma.rn.f32x2 %0,%1,%2,%3;" : "=l"(d) : "l"(a), "l"(b), "l"(c)); return d;
}
__device__ __forceinline__ u64 fmul2(u64 a, u64 b) {
    u64 d; asm("mul.rn.f32x2 %0,%1,%2;" : "=l"(d) : "l"(a), "l"(b)); return d;
}

// ---------------- kernel 0: fold conv bias + BN (+gamma) into weights ----------------
__global__ void fold_kernel(
    const float* __restrict__ wq, const float* __restrict__ bq,
    const float* __restrict__ qs, const float* __restrict__ qb,
    const float* __restrict__ qm, const float* __restrict__ qv,
    const float* __restrict__ wk, const float* __restrict__ bk,
    const float* __restrict__ ks, const float* __restrict__ kb,
    const float* __restrict__ km, const float* __restrict__ kv,
    const float* __restrict__ wv, const float* __restrict__ bv,
    const float* __restrict__ vs, const float* __restrict__ vb,
    const float* __restrict__ vm, const float* __restrict__ vv,
    const float* __restrict__ wp, const float* __restrict__ bp,
    const float* __restrict__ ps, const float* __restrict__ pb,
    const float* __restrict__ pm, const float* __restrict__ pv,
    const float* __restrict__ gamma)
{
    const float EPS = 1e-5f;
    int t = threadIdx.x;
    float gam = gamma[0];
    for (int i = t; i < CQn*CH; i += blockDim.x) {
        int c = i / CH;
        float iq = qs[c] * rsqrtf(qv[c] + EPS);
        float ik = ks[c] * rsqrtf(kv[c] + EPS);
        g_WQ[i] = wq[i] * iq;
        g_WK[i] = wk[i] * ik;
    }
    for (int c = t; c < CQn; c += blockDim.x) {
        float iq = qs[c] * rsqrtf(qv[c] + EPS);
        float ik = ks[c] * rsqrtf(kv[c] + EPS);
        g_CQ[c] = bq[c]*iq + qb[c] - qm[c]*iq;
        g_CK[c] = bk[c]*ik + kb[c] - km[c]*ik;
    }
    for (int i = t; i < CVn*CH; i += blockDim.x) {
        int c = i / CH;
        float iv = vs[c] * rsqrtf(vv[c] + EPS);
        g_WV[i] = wv[i] * iv;
    }
    for (int c = t; c < CVn; c += blockDim.x) {
        float iv = vs[c] * rsqrtf(vv[c] + EPS);
        g_CV[c] = bv[c]*iv + vb[c] - vm[c]*iv;
    }
    for (int i = t; i < CH*CVn; i += blockDim.x) {
        int c = i / CVn;
        float ip = ps[c] * rsqrtf(pv[c] + EPS);
        g_WP[i] = gam * ip * wp[i];
    }
    for (int c = t; c < CH; c += blockDim.x) {
        float ip = ps[c] * rsqrtf(pv[c] + EPS);
        g_CP[c] = gam * (bp[c]*ip + pb[c] - pm[c]*ip);
    }
}

// ---------------- kernel 1: compute Q (full-res) and pooled K/V ----------------
// One CTA per (batch, 2-row strip). strip = rows 2*h2, 2*h2+1 (128 pixels),
// pooled row h2 (32 pooled pixels).
__global__ __launch_bounds__(256) void prep_kernel(const float* __restrict__ mem)
{
    __shared__ float tile[CH*128];      // 32 KB: [ch][128 px]
    __shared__ float wqs[CQn*CH];
    __shared__ float wks[CQn*CH];
    __shared__ float wvs[CVn*CH];

    int t  = threadIdx.x;
    int b  = blockIdx.x >> 5;
    int h2 = blockIdx.x & 31;

    for (int i = t; i < CQn*CH; i += 256) { wqs[i] = g_WQ[i]; wks[i] = g_WK[i]; }
    for (int i = t; i < CVn*CH; i += 256) wvs[i] = g_WV[i];

    // load 64ch x 128px strip (each channel: 128 contiguous floats)
    const float4* src = (const float4*)(mem + (size_t)b*CH*HW + (size_t)h2*128);
    float4* t4 = (float4*)tile;
    for (int i = t; i < CH*32; i += 256) {
        int c = i >> 5, j = i & 31;
        t4[i] = src[(size_t)c*(HW/4) + j];
    }
    __syncthreads();

    // ---- Q: 8 ch x 128 px ; thread -> (4 ch, 1 px)
    {
        int p = t & 127, half = t >> 7;
        int oc0 = half * 4;
        float a0 = 0.f, a1 = 0.f, a2 = 0.f, a3 = 0.f;
        const float* w0 = &wqs[oc0*CH];
        #pragma unroll 8
        for (int ch = 0; ch < CH; ch++) {
            float m = tile[ch*128 + p];
            a0 += w0[ch      ]*m;
            a1 += w0[CH  +ch ]*m;
            a2 += w0[2*CH+ch ]*m;
            a3 += w0[3*CH+ch ]*m;
        }
        size_t n = (size_t)b*HW + h2*128 + p;
        float4 o = make_float4(a0 + g_CQ[oc0], a1 + g_CQ[oc0+1],
                               a2 + g_CQ[oc0+2], a3 + g_CQ[oc0+3]);
        *(float4*)&g_Q[n*CQn + oc0] = o;
    }

    // ---- K pooled: 8 ch x 32 pooled ; thread -> (1 ch, 1 pooled px, 4 src px)
    {
        int i = t & 31, oc = t >> 5;
        float a0 = 0.f, a1 = 0.f, a2 = 0.f, a3 = 0.f;
        const float* w = &wks[oc*CH];
        int p0 = 2*i, p2 = 64 + 2*i;
        #pragma unroll 4
        for (int ch = 0; ch < CH; ch++) {
            float wv_ = w[ch];
            const float* tr = &tile[ch*128];
            a0 += wv_*tr[p0];   a1 += wv_*tr[p0+1];
            a2 += wv_*tr[p2];   a3 += wv_*tr[p2+1];
        }
        float mx = fmaxf(fmaxf(a0,a1), fmaxf(a2,a3)) + g_CK[oc];
        g_K[((size_t)b*NP + h2*32 + i)*CQn + oc] = mx;
    }

    // ---- V pooled: 32 ch x 32 pooled ; thread -> (4 ch, 1 pooled px, 4 src px)
    {
        int i = t & 31, gr = t >> 5;
        int oc0 = gr * 4;
        float acc[4][4];
        #pragma unroll
        for (int a = 0; a < 4; a++)
            #pragma unroll
            for (int c = 0; c < 4; c++) acc[a][c] = 0.f;
        int p0 = 2*i, p2 = 64 + 2*i;
        #pragma unroll 2
        for (int ch = 0; ch < CH; ch++) {
            const float* tr = &tile[ch*128];
            float m0 = tr[p0], m1 = tr[p0+1], m2 = tr[p2], m3 = tr[p2+1];
            #pragma unroll
            for (int a = 0; a < 4; a++) {
                float wv_ = wvs[(oc0+a)*CH + ch];
                acc[a][0] += wv_*m0; acc[a][1] += wv_*m1;
                acc[a][2] += wv_*m2; acc[a][3] += wv_*m3;
            }
        }
        float4 o;
        float* op = &o.x;
        #pragma unroll
        for (int a = 0; a < 4; a++)
            op[a] = fmaxf(fmaxf(acc[a][0],acc[a][1]),
                          fmaxf(acc[a][2],acc[a][3])) + g_CV[oc0+a];
        *(float4*)&g_V[((size_t)b*NP + h2*32 + i)*CVn + oc0] = o;
    }
}

// ---------------- kernel 2: fused attention + projection + residual ----------------
// grid (16 q-tiles, 8 batches), 256 threads = 1 query/thread.
// K (32KB) + V (128KB) + folded wp (8KB) resident in SMEM; all reads broadcast.
#define SMEM_B_FLOATS (NP*CVn + NP*CQn + CH*CVn + CH)
#define SMEM_B_BYTES  (SMEM_B_FLOATS * 4)

__global__ __launch_bounds__(256) void attn_kernel(const float* __restrict__ x,
                                                   float* __restrict__ out)
{
    extern __shared__ float sm[];
    float* Vs  = sm;                    // [NP][32]
    float* Ksm = sm + NP*CVn;           // [NP][8]
    float* wps = Ksm + NP*CQn;          // [64][32]
    float* cps = wps + CH*CVn;          // [64]

    int t = threadIdx.x;
    int b = blockIdx.y;

    {
        const float4* sv = (const float4*)&g_V[(size_t)b*NP*CVn];
        float4* dv = (float4*)Vs;
        for (int i = t; i < NP*CVn/4; i += 256) dv[i] = sv[i];
        const float4* sk = (const float4*)&g_K[(size_t)b*NP*CQn];
        float4* dk = (float4*)Ksm;
        for (int i = t; i < NP*CQn/4; i += 256) dk[i] = sk[i];
        const float4* sw = (const float4*)g_WP;
        float4* dw = (float4*)wps;
        for (int i = t; i < CH*CVn/4; i += 256) dw[i] = sw[i];
        for (int i = t; i < CH; i += 256) cps[i] = g_CP[i];
    }
    __syncthreads();

    int nq = blockIdx.x*256 + t;   // pixel index within batch [0,4096)
    const float4* qp = (const float4*)&g_Q[((size_t)b*HW + nq)*CQn];
    float4 qA = qp[0], qB = qp[1];
    u64 q01 = pk2(qA.x, qA.y), q23 = pk2(qA.z, qA.w);
    u64 q45 = pk2(qB.x, qB.y), q67 = pk2(qB.z, qB.w);

    const ulonglong2* KK = (const ulonglong2*)Ksm;
    const ulonglong2* VV = (const ulonglong2*)Vs;

    // ---- pass 1: exact row max (robust against large BN scales)
    float mx = -1e30f;
    #pragma unroll 4
    for (int m = 0; m < NP; m++) {
        ulonglong2 k0 = KK[2*m], k1 = KK[2*m+1];
        u64 d = fmul2(q01, k0.x);
        d = ffma2(q23, k0.y, d);
        d = ffma2(q45, k1.x, d);
        d = ffma2(q67, k1.y, d);
        float lo, hi; upk2(d, lo, hi);
        mx = fmaxf(mx, lo + hi);
    }

    // ---- pass 2: exp + weighted V accumulation (packed f32x2 FMA)
    float s = 0.f;
    u64 acc[16];
    #pragma unroll
    for (int i = 0; i < 16; i++) acc[i] = 0ULL;   // {0.f, 0.f}
    #pragma unroll 2
    for (int m = 0; m < NP; m++) {
        ulonglong2 k0 = KK[2*m], k1 = KK[2*m+1];
        u64 d = fmul2(q01, k0.x);
        d = ffma2(q23, k0.y, d);
        d = ffma2(q45, k1.x, d);
        d = ffma2(q67, k1.y, d);
        float lo, hi; upk2(d, lo, hi);
        float e = __expf(lo + hi - mx);
        s += e;
        u64 e2 = pk2(e, e);
        const ulonglong2* vr = VV + (size_t)m*8;
        #pragma unroll
        for (int i = 0; i < 8; i++) {
            ulonglong2 v2 = vr[i];
            acc[2*i  ] = ffma2(e2, v2.x, acc[2*i  ]);
            acc[2*i+1] = ffma2(e2, v2.y, acc[2*i+1]);
        }
    }

    float inv = 1.0f / s;          // s >= 1 (max term contributes exp(0)=1)
    u64 inv2 = pk2(inv, inv);
    u64 gp[16];
    #pragma unroll
    for (int i = 0; i < 16; i++) gp[i] = fmul2(acc[i], inv2);

    // ---- folded projection (wp*BN*gamma) + residual
    const ulonglong2* W2 = (const ulonglong2*)wps;
    size_t base = (size_t)b*CH*HW + nq;
    #pragma unroll 4
    for (int c = 0; c < CH; c++) {
        const ulonglong2* wr = W2 + (size_t)c*8;
        u64 d = 0ULL;
        #pragma unroll
        for (int i = 0; i < 8; i++) {
            ulonglong2 w2 = wr[i];
            d = ffma2(gp[2*i  ], w2.x, d);
            d = ffma2(gp[2*i+1], w2.y, d);
        }
        float lo, hi; upk2(d, lo, hi);
        float val = lo + hi + cps[c];
        out[base + (size_t)c*HW] = __ldg(&x[base + (size_t)c*HW]) + val;
    }
}

// ---------------- launch ----------------
extern "C" void kernel_launch(void* const* d_in, const int* in_sizes, int n_in,
                              void* d_out, int out_size)
{
    (void)in_sizes; (void)n_in; (void)out_size;
    const float* x   = (const float*)d_in[0];
    const float* mem = (const float*)d_in[1];

    cudaFuncSetAttribute(attn_kernel,
                         cudaFuncAttributeMaxDynamicSharedMemorySize, SMEM_B_BYTES);

    fold_kernel<<<1, 256>>>(
        (const float*)d_in[2],  (const float*)d_in[3],  (const float*)d_in[4],
        (const float*)d_in[5],  (const float*)d_in[6],  (const float*)d_in[7],
        (const float*)d_in[8],  (const float*)d_in[9],  (const float*)d_in[10],
        (const float*)d_in[11], (const float*)d_in[12], (const float*)d_in[13],
        (const float*)d_in[14], (const float*)d_in[15], (const float*)d_in[16],
        (const float*)d_in[17], (const float*)d_in[18], (const float*)d_in[19],
        (const float*)d_in[20], (const float*)d_in[21], (const float*)d_in[22],
        (const float*)d_in[23], (const float*)d_in[24], (const float*)d_in[25],
        (const float*)d_in[26]);

    prep_kernel<<<BATCH*32, 256>>>(mem);

    attn_kernel<<<dim3(16, BATCH), 256, SMEM_B_BYTES>>>(x, (float*)d_out);
}

// round 2
// speedup vs baseline: 1.0920x; 1.0920x over previous
#include <cuda_runtime.h>

typedef unsigned long long u64;

#define BATCH 8
#define CH    64
#define HW    4096
#define CQn   8
#define CVn   32
#define NP    1024   // pooled pixels per batch (32x32)
#define EPSBN 1e-5f
#define LOG2E 1.4426950408889634f

// ---------------- precomputed Q/K/V (K pre-scaled by log2e) ----------------
__device__ float g_Q[(size_t)BATCH*HW*CQn];   // [b][n][8]
__device__ float g_K[(size_t)BATCH*NP*CQn];   // [b][m][8]  (x log2e)
__device__ float g_V[(size_t)BATCH*NP*CVn];   // [b][m][32]

// ---------------- f32x2 helpers (Blackwell packed fp32) ----------------
__device__ __forceinline__ u64 pk2(float lo, float hi) {
    u64 r; asm("mov.b64 %0,{%1,%2};" : "=l"(r) : "f"(lo), "f"(hi)); return r;
}
__device__ __forceinline__ void upk2(u64 v, float& lo, float& hi) {
    asm("mov.b64 {%0,%1},%2;" : "=f"(lo), "=f"(hi) : "l"(v));
}
__device__ __forceinline__ u64 ffma2(u64 a, u64 b, u64 c) {
    u64 d; asm("fma.rn.f32x2 %0,%1,%2,%3;" : "=l"(d) : "l"(a), "l"(b), "l"(c)); return d;
}
__device__ __forceinline__ u64 fmul2(u64 a, u64 b) {
    u64 d; asm("mul.rn.f32x2 %0,%1,%2;" : "=l"(d) : "l"(a), "l"(b)); return d;
}
__device__ __forceinline__ float ex2(float x) {
    float y; asm("ex2.approx.f32 %0,%1;" : "=f"(y) : "f"(x)); return y;
}

// ---------------- kernel 1: Q (full-res) + pooled K/V, BN folded in-CTA ----
// One CTA per (batch, 2-row strip): rows 2*h2, 2*h2+1 (128 px), pooled row h2.
__global__ __launch_bounds__(256) void prep_kernel(
    const float* __restrict__ mem,
    const float* __restrict__ wq, const float* __restrict__ bq,
    const float* __restrict__ qs, const float* __restrict__ qb,
    const float* __restrict__ qm, const float* __restrict__ qv,
    const float* __restrict__ wk, const float* __restrict__ bk,
    const float* __restrict__ ks, const float* __restrict__ kb,
    const float* __restrict__ km, const float* __restrict__ kv,
    const float* __restrict__ wv, const float* __restrict__ bv,
    const float* __restrict__ vs, const float* __restrict__ vb,
    const float* __restrict__ vm, const float* __restrict__ vv)
{
    __shared__ float tile[CH*128];      // 32 KB: [ch][128 px]
    __shared__ float wqs[CQn*CH];
    __shared__ float wks[CQn*CH];
    __shared__ float wvs[CVn*CH];
    __shared__ float cqs[CQn], cks[CQn], cvs[CVn];

    int t  = threadIdx.x;
    int b  = blockIdx.x >> 5;
    int h2 = blockIdx.x & 31;

    // fold BN into weights (per-CTA, tiny)
    for (int i = t; i < CQn*CH; i += 256) {
        int c = i >> 6;
        float iq = qs[c] * rsqrtf(qv[c] + EPSBN);
        float ik = ks[c] * rsqrtf(kv[c] + EPSBN);
        wqs[i] = wq[i] * iq;
        wks[i] = wk[i] * ik * LOG2E;
    }
    for (int i = t; i < CVn*CH; i += 256) {
        int c = i >> 6;
        float iv = vs[c] * rsqrtf(vv[c] + EPSBN);
        wvs[i] = wv[i] * iv;
    }
    if (t < CQn) {
        float iq = qs[t] * rsqrtf(qv[t] + EPSBN);
        float ik = ks[t] * rsqrtf(kv[t] + EPSBN);
        cqs[t] = bq[t]*iq + qb[t] - qm[t]*iq;
        cks[t] = (bk[t]*ik + kb[t] - km[t]*ik) * LOG2E;
    }
    if (t < CVn) {
        float iv = vs[t] * rsqrtf(vv[t] + EPSBN);
        cvs[t] = bv[t]*iv + vb[t] - vm[t]*iv;
    }

    // load 64ch x 128px strip (each channel: 128 contiguous floats)
    const float4* src = (const float4*)(mem + (size_t)b*CH*HW + (size_t)h2*128);
    float4* t4 = (float4*)tile;
    for (int i = t; i < CH*32; i += 256) {
        int c = i >> 5, j = i & 31;
        t4[i] = src[(size_t)c*(HW/4) + j];
    }
    __syncthreads();

    // ---- Q: 8 ch x 128 px ; thread -> (4 ch, 1 px)
    {
        int p = t & 127, half = t >> 7;
        int oc0 = half * 4;
        float a0 = 0.f, a1 = 0.f, a2 = 0.f, a3 = 0.f;
        const float* w0 = &wqs[oc0*CH];
        #pragma unroll 8
        for (int ch = 0; ch < CH; ch++) {
            float m = tile[ch*128 + p];
            a0 += w0[ch      ]*m;
            a1 += w0[CH  +ch ]*m;
            a2 += w0[2*CH+ch ]*m;
            a3 += w0[3*CH+ch ]*m;
        }
        size_t n = (size_t)b*HW + h2*128 + p;
        float4 o = make_float4(a0 + cqs[oc0], a1 + cqs[oc0+1],
                               a2 + cqs[oc0+2], a3 + cqs[oc0+3]);
        *(float4*)&g_Q[n*CQn + oc0] = o;
    }

    // ---- K pooled: 8 ch x 32 pooled ; thread -> (1 ch, 1 pooled px, 4 src px)
    {
        int i = t & 31, oc = t >> 5;
        float a0 = 0.f, a1 = 0.f, a2 = 0.f, a3 = 0.f;
        const float* w = &wks[oc*CH];
        int p0 = 2*i, p2 = 64 + 2*i;
        #pragma unroll 4
        for (int ch = 0; ch < CH; ch++) {
            float wv_ = w[ch];
            const float* tr = &tile[ch*128];
            a0 += wv_*tr[p0];   a1 += wv_*tr[p0+1];
            a2 += wv_*tr[p2];   a3 += wv_*tr[p2+1];
        }
        float mx = fmaxf(fmaxf(a0,a1), fmaxf(a2,a3)) + cks[oc];
        g_K[((size_t)b*NP + h2*32 + i)*CQn + oc] = mx;
    }

    // ---- V pooled: 32 ch x 32 pooled ; thread -> (4 ch, 1 pooled px, 4 src px)
    {
        int i = t & 31, gr = t >> 5;
        int oc0 = gr * 4;
        float acc[4][4];
        #pragma unroll
        for (int a = 0; a < 4; a++)
            #pragma unroll
            for (int c = 0; c < 4; c++) acc[a][c] = 0.f;
        int p0 = 2*i, p2 = 64 + 2*i;
        #pragma unroll 2
        for (int ch = 0; ch < CH; ch++) {
            const float* tr = &tile[ch*128];
            float m0 = tr[p0], m1 = tr[p0+1], m2 = tr[p2], m3 = tr[p2+1];
            #pragma unroll
            for (int a = 0; a < 4; a++) {
                float wv_ = wvs[(oc0+a)*CH + ch];
                acc[a][0] += wv_*m0; acc[a][1] += wv_*m1;
                acc[a][2] += wv_*m2; acc[a][3] += wv_*m3;
            }
        }
        float4 o;
        float* op = &o.x;
        #pragma unroll
        for (int a = 0; a < 4; a++)
            op[a] = fmaxf(fmaxf(acc[a][0],acc[a][1]),
                          fmaxf(acc[a][2],acc[a][3])) + cvs[oc0+a];
        *(float4*)&g_V[((size_t)b*NP + h2*32 + i)*CVn + oc0] = o;
    }
}

// ---------------- kernel 2: fused attention + projection + residual -------
// grid (16 q-tiles, 8 batches), 256 threads = 1 query/thread.
// K (32KB) + V (128KB) + folded wp (8KB) resident in SMEM; reads broadcast.
// Single-pass online softmax, chunks of 16 keys.
#define CHUNK 16
#define SMEM_B_FLOATS (NP*CVn + NP*CQn + CH*CVn + CH)
#define SMEM_B_BYTES  (SMEM_B_FLOATS * 4)

__global__ __launch_bounds__(256) void attn_kernel(
    const float* __restrict__ x, float* __restrict__ out,
    const float* __restrict__ wp, const float* __restrict__ bp,
    const float* __restrict__ ps, const float* __restrict__ pb,
    const float* __restrict__ pm, const float* __restrict__ pv,
    const float* __restrict__ gamma)
{
    extern __shared__ float sm[];
    float* Vs  = sm;                    // [NP][32]
    float* Ksm = sm + NP*CVn;           // [NP][8]
    float* wps = Ksm + NP*CQn;          // [64][32]
    float* cps = wps + CH*CVn;          // [64]

    int t = threadIdx.x;
    int b = blockIdx.y;
    float gam = gamma[0];

    {
        const float4* sv = (const float4*)&g_V[(size_t)b*NP*CVn];
        float4* dv = (float4*)Vs;
        for (int i = t; i < NP*CVn/4; i += 256) dv[i] = sv[i];
        const float4* sk = (const float4*)&g_K[(size_t)b*NP*CQn];
        float4* dk = (float4*)Ksm;
        for (int i = t; i < NP*CQn/4; i += 256) dk[i] = sk[i];
        // fold BN+gamma into projection weights (per-CTA)
        for (int i = t; i < CH*CVn; i += 256) {
            int c = i >> 5;
            float ip = ps[c] * rsqrtf(pv[c] + EPSBN);
            wps[i] = gam * ip * wp[i];
        }
        for (int c = t; c < CH; c += 256) {
            float ip = ps[c] * rsqrtf(pv[c] + EPSBN);
            cps[c] = gam * (bp[c]*ip + pb[c] - pm[c]*ip);
        }
    }
    __syncthreads();

    int nq = blockIdx.x*256 + t;   // pixel index within batch [0,4096)
    const float4* qp = (const float4*)&g_Q[((size_t)b*HW + nq)*CQn];
    float4 qA = qp[0], qB = qp[1];
    u64 q01 = pk2(qA.x, qA.y), q23 = pk2(qA.z, qA.w);
    u64 q45 = pk2(qB.x, qB.y), q67 = pk2(qB.z, qB.w);

    const ulonglong2* KK = (const ulonglong2*)Ksm;
    const ulonglong2* VV = (const ulonglong2*)Vs;

    // ---- single pass: online softmax (chunked) + weighted V accumulation
    float mx = -1e30f;
    float s  = 0.f;
    u64 acc[16];
    #pragma unroll
    for (int i = 0; i < 16; i++) acc[i] = 0ULL;

    #pragma unroll 1
    for (int m0 = 0; m0 < NP; m0 += CHUNK) {
        const ulonglong2* kr = KK + 2*(size_t)m0;
        float l[CHUNK];
        float cmax = -1e30f;
        #pragma unroll
        for (int j = 0; j < CHUNK; j++) {
            ulonglong2 k0 = kr[2*j], k1 = kr[2*j+1];
            u64 d = fmul2(q01, k0.x);
            d = ffma2(q23, k0.y, d);
            d = ffma2(q45, k1.x, d);
            d = ffma2(q67, k1.y, d);
            float lo, hi; upk2(d, lo, hi);
            l[j] = lo + hi;                 // log2-scale logit
            cmax = fmaxf(cmax, l[j]);
        }
        if (cmax > mx) {                    // rare after warm-up
            float f = ex2(mx - cmax);
            mx = cmax;
            s *= f;
            u64 f2 = pk2(f, f);
            #pragma unroll
            for (int i = 0; i < 16; i++) acc[i] = fmul2(acc[i], f2);
        }
        #pragma unroll
        for (int j = 0; j < CHUNK; j++) {
            float e = ex2(l[j] - mx);
            s += e;
            u64 e2 = pk2(e, e);
            const ulonglong2* vr = VV + (size_t)(m0 + j)*8;
            #pragma unroll
            for (int i = 0; i < 8; i++) {
                ulonglong2 v2 = vr[i];
                acc[2*i  ] = ffma2(e2, v2.x, acc[2*i  ]);
                acc[2*i+1] = ffma2(e2, v2.y, acc[2*i+1]);
            }
        }
    }

    float inv = 1.0f / s;          // s >= 1 (max term contributes 2^0 = 1)
    u64 inv2 = pk2(inv, inv);
    u64 gp[16];
    #pragma unroll
    for (int i = 0; i < 16; i++) gp[i] = fmul2(acc[i], inv2);

    // ---- folded projection (wp*BN*gamma) + residual
    const ulonglong2* W2 = (const ulonglong2*)wps;
    size_t base = (size_t)b*CH*HW + nq;
    #pragma unroll 4
    for (int c = 0; c < CH; c++) {
        const ulonglong2* wr = W2 + (size_t)c*8;
        u64 d = 0ULL;
        #pragma unroll
        for (int i = 0; i < 8; i++) {
            ulonglong2 w2 = wr[i];
            d = ffma2(gp[2*i  ], w2.x, d);
            d = ffma2(gp[2*i+1], w2.y, d);
        }
        float lo, hi; upk2(d, lo, hi);
        float val = lo + hi + cps[c];
        out[base + (size_t)c*HW] = __ldg(&x[base + (size_t)c*HW]) + val;
    }
}

// ---------------- launch ----------------
extern "C" void kernel_launch(void* const* d_in, const int* in_sizes, int n_in,
                              void* d_out, int out_size)
{
    (void)in_sizes; (void)n_in; (void)out_size;
    const float* x   = (const float*)d_in[0];
    const float* mem = (const float*)d_in[1];

    cudaFuncSetAttribute(attn_kernel,
                         cudaFuncAttributeMaxDynamicSharedMemorySize, SMEM_B_BYTES);

    prep_kernel<<<BATCH*32, 256>>>(mem,
        (const float*)d_in[2],  (const float*)d_in[3],  (const float*)d_in[4],
        (const float*)d_in[5],  (const float*)d_in[6],  (const float*)d_in[7],
        (const float*)d_in[8],  (const float*)d_in[9],  (const float*)d_in[10],
        (const float*)d_in[11], (const float*)d_in[12], (const float*)d_in[13],
        (const float*)d_in[14], (const float*)d_in[15], (const float*)d_in[16],
        (const float*)d_in[17], (const float*)d_in[18], (const float*)d_in[19]);

    attn_kernel<<<dim3(16, BATCH), 256, SMEM_B_BYTES>>>(x, (float*)d_out,
        (const float*)d_in[20], (const float*)d_in[21], (const float*)d_in[22],
        (const float*)d_in[23], (const float*)d_in[24], (const float*)d_in[25],
        (const float*)d_in[26]);
}

// round 3
// speedup vs baseline: 1.0954x; 1.0031x over previous
#include <cuda_runtime.h>

typedef unsigned long long u64;

#define BATCH 8
#define CH    64
#define HW    4096
#define CQn   8
#define CVn   32
#define NP    1024   // pooled pixels per batch (32x32)
#define EPSBN 1e-5f
#define LOG2E 1.4426950408889634f

// ---------------- precomputed Q/K/V (K pre-scaled by log2e) ----------------
__device__ float g_Q[(size_t)BATCH*HW*CQn];   // [b][n][8]
__device__ float g_K[(size_t)BATCH*NP*CQn];   // [b][m][8]  (x log2e)
__device__ float g_V[(size_t)BATCH*NP*CVn];   // [b][m][32]

// ---------------- f32x2 helpers (Blackwell packed fp32) ----------------
__device__ __forceinline__ u64 pk2(float lo, float hi) {
    u64 r; asm("mov.b64 %0,{%1,%2};" : "=l"(r) : "f"(lo), "f"(hi)); return r;
}
__device__ __forceinline__ void upk2(u64 v, float& lo, float& hi) {
    asm("mov.b64 {%0,%1},%2;" : "=f"(lo), "=f"(hi) : "l"(v));
}
__device__ __forceinline__ u64 ffma2(u64 a, u64 b, u64 c) {
    u64 d; asm("fma.rn.f32x2 %0,%1,%2,%3;" : "=l"(d) : "l"(a), "l"(b), "l"(c)); return d;
}
__device__ __forceinline__ u64 fmul2(u64 a, u64 b) {
    u64 d; asm("mul.rn.f32x2 %0,%1,%2;" : "=l"(d) : "l"(a), "l"(b)); return d;
}
__device__ __forceinline__ float ex2(float x) {
    float y; asm("ex2.approx.f32 %0,%1;" : "=f"(y) : "f"(x)); return y;
}

// ---------------- kernel 1: Q (full-res) + pooled K/V, BN folded in-CTA ----
// One CTA per (batch, 2-row strip): rows 2*h2, 2*h2+1 (128 px), pooled row h2.
__global__ __launch_bounds__(256) void prep_kernel(
    const float* __restrict__ mem,
    const float* __restrict__ wq, const float* __restrict__ bq,
    const float* __restrict__ qs, const float* __restrict__ qb,
    const float* __restrict__ qm, const float* __restrict__ qv,
    const float* __restrict__ wk, const float* __restrict__ bk,
    const float* __restrict__ ks, const float* __restrict__ kb,
    const float* __restrict__ km, const float* __restrict__ kv,
    const float* __restrict__ wv, const float* __restrict__ bv,
    const float* __restrict__ vs, const float* __restrict__ vb,
    const float* __restrict__ vm, const float* __restrict__ vv)
{
    __shared__ float tile[CH*128];      // 32 KB: [ch][128 px]
    __shared__ float wqs[CQn*CH];
    __shared__ float wks[CQn*CH];
    __shared__ float wvs[CVn*CH];
    __shared__ float cqs[CQn], cks[CQn], cvs[CVn];

    int t  = threadIdx.x;
    int b  = blockIdx.x >> 5;
    int h2 = blockIdx.x & 31;

    // fold BN into weights (per-CTA, tiny)
    for (int i = t; i < CQn*CH; i += 256) {
        int c = i >> 6;
        float iq = qs[c] * rsqrtf(qv[c] + EPSBN);
        float ik = ks[c] * rsqrtf(kv[c] + EPSBN);
        wqs[i] = wq[i] * iq;
        wks[i] = wk[i] * ik * LOG2E;
    }
    for (int i = t; i < CVn*CH; i += 256) {
        int c = i >> 6;
        float iv = vs[c] * rsqrtf(vv[c] + EPSBN);
        wvs[i] = wv[i] * iv;
    }
    if (t < CQn) {
        float iq = qs[t] * rsqrtf(qv[t] + EPSBN);
        float ik = ks[t] * rsqrtf(kv[t] + EPSBN);
        cqs[t] = bq[t]*iq + qb[t] - qm[t]*iq;
        cks[t] = (bk[t]*ik + kb[t] - km[t]*ik) * LOG2E;
    }
    if (t < CVn) {
        float iv = vs[t] * rsqrtf(vv[t] + EPSBN);
        cvs[t] = bv[t]*iv + vb[t] - vm[t]*iv;
    }

    // load 64ch x 128px strip (each channel: 128 contiguous floats)
    const float4* src = (const float4*)(mem + (size_t)b*CH*HW + (size_t)h2*128);
    float4* t4 = (float4*)tile;
    for (int i = t; i < CH*32; i += 256) {
        int c = i >> 5, j = i & 31;
        t4[i] = src[(size_t)c*(HW/4) + j];
    }
    __syncthreads();

    // ---- Q: 8 ch x 128 px ; thread -> (4 ch, 1 px)
    {
        int p = t & 127, half = t >> 7;
        int oc0 = half * 4;
        float a0 = 0.f, a1 = 0.f, a2 = 0.f, a3 = 0.f;
        const float* w0 = &wqs[oc0*CH];
        #pragma unroll 8
        for (int ch = 0; ch < CH; ch++) {
            float m = tile[ch*128 + p];
            a0 += w0[ch      ]*m;
            a1 += w0[CH  +ch ]*m;
            a2 += w0[2*CH+ch ]*m;
            a3 += w0[3*CH+ch ]*m;
        }
        size_t n = (size_t)b*HW + h2*128 + p;
        float4 o = make_float4(a0 + cqs[oc0], a1 + cqs[oc0+1],
                               a2 + cqs[oc0+2], a3 + cqs[oc0+3]);
        *(float4*)&g_Q[n*CQn + oc0] = o;
    }

    // ---- K pooled: 8 ch x 32 pooled ; thread -> (1 ch, 1 pooled px, 4 src px)
    {
        int i = t & 31, oc = t >> 5;
        float a0 = 0.f, a1 = 0.f, a2 = 0.f, a3 = 0.f;
        const float* w = &wks[oc*CH];
        int p0 = 2*i, p2 = 64 + 2*i;
        #pragma unroll 4
        for (int ch = 0; ch < CH; ch++) {
            float wv_ = w[ch];
            const float* tr = &tile[ch*128];
            a0 += wv_*tr[p0];   a1 += wv_*tr[p0+1];
            a2 += wv_*tr[p2];   a3 += wv_*tr[p2+1];
        }
        float mx = fmaxf(fmaxf(a0,a1), fmaxf(a2,a3)) + cks[oc];
        g_K[((size_t)b*NP + h2*32 + i)*CQn + oc] = mx;
    }

    // ---- V pooled: 32 ch x 32 pooled ; thread -> (4 ch, 1 pooled px, 4 src px)
    {
        int i = t & 31, gr = t >> 5;
        int oc0 = gr * 4;
        float acc[4][4];
        #pragma unroll
        for (int a = 0; a < 4; a++)
            #pragma unroll
            for (int c = 0; c < 4; c++) acc[a][c] = 0.f;
        int p0 = 2*i, p2 = 64 + 2*i;
        #pragma unroll 2
        for (int ch = 0; ch < CH; ch++) {
            const float* tr = &tile[ch*128];
            float m0 = tr[p0], m1 = tr[p0+1], m2 = tr[p2], m3 = tr[p2+1];
            #pragma unroll
            for (int a = 0; a < 4; a++) {
                float wv_ = wvs[(oc0+a)*CH + ch];
                acc[a][0] += wv_*m0; acc[a][1] += wv_*m1;
                acc[a][2] += wv_*m2; acc[a][3] += wv_*m3;
            }
        }
        float4 o;
        float* op = &o.x;
        #pragma unroll
        for (int a = 0; a < 4; a++)
            op[a] = fmaxf(fmaxf(acc[a][0],acc[a][1]),
                          fmaxf(acc[a][2],acc[a][3])) + cvs[oc0+a];
        *(float4*)&g_V[((size_t)b*NP + h2*32 + i)*CVn + oc0] = o;
    }
}

// ---------------- kernel 2: fused attention + projection + residual -------
// grid (16 q-tiles, 8 batches), 256 threads = 1 query/thread.
// K (32KB) + V (128KB) + folded wp (8KB) resident in SMEM; reads broadcast.
// Single-pass online softmax, chunks of 16 keys.
#define CHUNK 16
#define SMEM_B_FLOATS (NP*CVn + NP*CQn + CH*CVn + CH)
#define SMEM_B_BYTES  (SMEM_B_FLOATS * 4)

__global__ __launch_bounds__(256) void attn_kernel(
    const float* __restrict__ x, float* __restrict__ out,
    const float* __restrict__ wp, const float* __restrict__ bp,
    const float* __restrict__ ps, const float* __restrict__ pb,
    const float* __restrict__ pm, const float* __restrict__ pv,
    const float* __restrict__ gamma)
{
    extern __shared__ float sm[];
    float* Vs  = sm;                    // [NP][32]
    float* Ksm = sm + NP*CVn;           // [NP][8]
    float* wps = Ksm + NP*CQn;          // [64][32]
    float* cps = wps + CH*CVn;          // [64]

    int t = threadIdx.x;
    int b = blockIdx.y;
    float gam = gamma[0];

    {
        const float4* sv = (const float4*)&g_V[(size_t)b*NP*CVn];
        float4* dv = (float4*)Vs;
        for (int i = t; i < NP*CVn/4; i += 256) dv[i] = sv[i];
        const float4* sk = (const float4*)&g_K[(size_t)b*NP*CQn];
        float4* dk = (float4*)Ksm;
        for (int i = t; i < NP*CQn/4; i += 256) dk[i] = sk[i];
        // fold BN+gamma into projection weights (per-CTA)
        for (int i = t; i < CH*CVn; i += 256) {
            int c = i >> 5;
            float ip = ps[c] * rsqrtf(pv[c] + EPSBN);
            wps[i] = gam * ip * wp[i];
        }
        for (int c = t; c < CH; c += 256) {
            float ip = ps[c] * rsqrtf(pv[c] + EPSBN);
            cps[c] = gam * (bp[c]*ip + pb[c] - pm[c]*ip);
        }
    }
    __syncthreads();

    int nq = blockIdx.x*256 + t;   // pixel index within batch [0,4096)
    const float4* qp = (const float4*)&g_Q[((size_t)b*HW + nq)*CQn];
    float4 qA = qp[0], qB = qp[1];
    u64 q01 = pk2(qA.x, qA.y), q23 = pk2(qA.z, qA.w);
    u64 q45 = pk2(qB.x, qB.y), q67 = pk2(qB.z, qB.w);

    const ulonglong2* KK = (const ulonglong2*)Ksm;
    const ulonglong2* VV = (const ulonglong2*)Vs;

    // ---- single pass: online softmax (chunked) + weighted V accumulation
    float mx = -1e30f;
    float s  = 0.f;
    u64 acc[16];
    #pragma unroll
    for (int i = 0; i < 16; i++) acc[i] = 0ULL;

    #pragma unroll 1
    for (int m0 = 0; m0 < NP; m0 += CHUNK) {
        const ulonglong2* kr = KK + 2*(size_t)m0;
        float l[CHUNK];
        float cmax = -1e30f;
        #pragma unroll
        for (int j = 0; j < CHUNK; j++) {
            ulonglong2 k0 = kr[2*j], k1 = kr[2*j+1];
            u64 d = fmul2(q01, k0.x);
            d = ffma2(q23, k0.y, d);
            d = ffma2(q45, k1.x, d);
            d = ffma2(q67, k1.y, d);
            float lo, hi; upk2(d, lo, hi);
            l[j] = lo + hi;                 // log2-scale logit
            cmax = fmaxf(cmax, l[j]);
        }
        if (cmax > mx) {                    // rare after warm-up
            float f = ex2(mx - cmax);
            mx = cmax;
            s *= f;
            u64 f2 = pk2(f, f);
            #pragma unroll
            for (int i = 0; i < 16; i++) acc[i] = fmul2(acc[i], f2);
        }
        #pragma unroll
        for (int j = 0; j < CHUNK; j++) {
            float e = ex2(l[j] - mx);
            s += e;
            u64 e2 = pk2(e, e);
            const ulonglong2* vr = VV + (size_t)(m0 + j)*8;
            #pragma unroll
            for (int i = 0; i < 8; i++) {
                ulonglong2 v2 = vr[i];
                acc[2*i  ] = ffma2(e2, v2.x, acc[2*i  ]);
                acc[2*i+1] = ffma2(e2, v2.y, acc[2*i+1]);
            }
        }
    }

    float inv = 1.0f / s;          // s >= 1 (max term contributes 2^0 = 1)
    u64 inv2 = pk2(inv, inv);
    u64 gp[16];
    #pragma unroll
    for (int i = 0; i < 16; i++) gp[i] = fmul2(acc[i], inv2);

    // ---- folded projection (wp*BN*gamma) + residual
    const ulonglong2* W2 = (const ulonglong2*)wps;
    size_t base = (size_t)b*CH*HW + nq;
    #pragma unroll 4
    for (int c = 0; c < CH; c++) {
        const ulonglong2* wr = W2 + (size_t)c*8;
        u64 d = 0ULL;
        #pragma unroll
        for (int i = 0; i < 8; i++) {
            ulonglong2 w2 = wr[i];
            d = ffma2(gp[2*i  ], w2.x, d);
            d = ffma2(gp[2*i+1], w2.y, d);
        }
        float lo, hi; upk2(d, lo, hi);
        float val = lo + hi + cps[c];
        out[base + (size_t)c*HW] = __ldg(&x[base + (size_t)c*HW]) + val;
    }
}

// ---------------- launch ----------------
extern "C" void kernel_launch(void* const* d_in, const int* in_sizes, int n_in,
                              void* d_out, int out_size)
{
    (void)in_sizes; (void)n_in; (void)out_size;
    const float* x   = (const float*)d_in[0];
    const float* mem = (const float*)d_in[1];

    cudaFuncSetAttribute(attn_kernel,
                         cudaFuncAttributeMaxDynamicSharedMemorySize, SMEM_B_BYTES);

    prep_kernel<<<BATCH*32, 256>>>(mem,
        (const float*)d_in[2],  (const float*)d_in[3],  (const float*)d_in[4],
        (const float*)d_in[5],  (const float*)d_in[6],  (const float*)d_in[7],
        (const float*)d_in[8],  (const float*)d_in[9],  (const float*)d_in[10],
        (const float*)d_in[11], (const float*)d_in[12], (const float*)d_in[13],
        (const float*)d_in[14], (const float*)d_in[15], (const float*)d_in[16],
        (const float*)d_in[17], (const float*)d_in[18], (const float*)d_in[19]);

    attn_kernel<<<dim3(16, BATCH), 256, SMEM_B_BYTES>>>(x, (float*)d_out,
        (const float*)d_in[20], (const float*)d_in[21], (const float*)d_in[22],
        (const float*)d_in[23], (const float*)d_in[24], (const float*)d_in[25],
        (const float*)d_in[26]);
}